// round 4
// baseline (speedup 1.0000x reference)
#include <cuda_runtime.h>

// GreedyInvasionMemory: sequential scan, d_k = d_v = 128, seq = 2048.
// Output layout (float32): [costs (2048) | updated 0/1 (2048) | J row-major (128x128)]
//
// Single-CTA persistent kernel, 256 threads. Thread t owns row r = t&127 and
// column half [64*(t>>7), +64) of Sqq, Sqv, J — register-resident as packed
// f32x2 (u64 carriers) driven by fma.rn.f32x2 (FFMA2; ptxas never emits it
// from C++).
//
// Matrices kept UNNORMALIZED (plain outer-product sums): all decision
// quantities (wf/wi signs, margin sign, ==0 tests) are invariant under the
// uniform 1/l scaling; only the reported cost divides by l.
//
// tr(J Sqq J^T), tr(J Sqv), tr(Svv) maintained by EXACT scalar recurrences:
//   Sqq += q q^T  =>  A_JJ = T + |Jq|^2 ;  Sqv += q v^T => s_J += v.(Jq)
//   J' = aJ + b v k^T => T' = a^2 A_JJ + 2ab A_Jl + b^2 A_ll ; s_J' = a s_J + b s_l
// so no O(d^3) work exists anywhere.
//
// Decisions (a, b, updated) are computed REDUNDANTLY by all threads from the
// shared per-warp partials + fp32 shadows of the state (published by thread 0
// one step earlier) — removes the tail barrier and the serial thread-0
// decision from the critical path. fp64 master state + cost output live in
// thread 0 only. All cross-step shared arrays are parity double-buffered.

#define D    128
#define SEQ  2048
#define NT   256
#define CP2  32      // column PAIRS per thread (64 columns)
#define NW   8       // warps

typedef unsigned long long u64;

__device__ __forceinline__ u64 ffma2(u64 a, u64 b, u64 c) {
    u64 r; asm("fma.rn.f32x2 %0, %1, %2, %3;" : "=l"(r) : "l"(a), "l"(b), "l"(c));
    return r;
}
__device__ __forceinline__ u64 fmul2(u64 a, u64 b) {
    u64 r; asm("mul.rn.f32x2 %0, %1, %2;" : "=l"(r) : "l"(a), "l"(b));
    return r;
}
__device__ __forceinline__ u64 pack2(float x, float y) {
    u64 r; asm("mov.b64 %0, {%1, %2};" : "=l"(r) : "f"(x), "f"(y));
    return r;
}
__device__ __forceinline__ void unpack2(u64 v, float& x, float& y) {
    asm("mov.b64 {%0, %1}, %2;" : "=f"(x), "=f"(y) : "l"(v));
}
__device__ __forceinline__ float hadd2(u64 v) {
    float x, y; unpack2(v, x, y); return x + y;
}
__device__ __forceinline__ float sum8(const float* p) {
    const float4 a = *(const float4*)p, b = *(const float4*)(p + 4);
    return ((a.x + a.y) + (a.z + a.w)) + ((b.x + b.y) + (b.z + b.w));
}

__global__ __launch_bounds__(NT, 1)
void gim_kernel(const float* __restrict__ qg, const float* __restrict__ kg,
                const float* __restrict__ vg, float* __restrict__ out)
{
    __shared__ __align__(16) float sq[2][D], sk[2][D], sv[2][D];
    __shared__ __align__(16) float su[D];
    __shared__ __align__(16) float pu[2 * D], pg[2 * D];
    // parity-double-buffered per-warp partials (read one step after write,
    // with only 3 barriers in between -> need 2-deep buffering):
    __shared__ __align__(16) float wA0[2][NW], wA1[2][NW], wA2[2][NW], wC[2][NW];
    __shared__ __align__(16) float wB0[2][4], wB1[2][4];
    __shared__ __align__(16) float sTf[2][2];   // fp32 shadows {T, sJ} per parity

    const int tid  = threadIdx.x;
    const int r    = tid & (D - 1);
    const int sub  = tid >> 7;          // 0 or 1
    const int C0   = sub * 64;
    const int warp = tid >> 5;
    const int lane = tid & 31;

    u64 Sqq2[CP2], Sqv2[CP2], Jm2[CP2];
#pragma unroll
    for (int i = 0; i < CP2; i++) { Sqq2[i] = 0ull; Sqv2[i] = 0ull; Jm2[i] = 0ull; }

    // fp64 master state (meaningful only in thread 0)
    double Tacc = 0.0, sJ = 0.0, trSvv = 0.0;

    // Pre-loop: step 0 -> buf0, step 1 -> prefetch regs; init shadows.
    float rq = 0.f, rk = 0.f, rv = 0.f;
    if (tid < D) {
        sq[0][tid] = qg[tid]; sk[0][tid] = kg[tid]; sv[0][tid] = vg[tid];
        rq = qg[D + tid]; rk = kg[D + tid]; rv = vg[D + tid];
    }
    if (tid == 0) { sTf[0][0] = 0.f; sTf[0][1] = 0.f; sTf[1][0] = 0.f; sTf[1][1] = 0.f; }
    __syncthreads();

    for (int l = 0; l < SEQ; l++) {
        const int par = l & 1, nxt = par ^ 1;
        const float* Q = sq[par];
        const float* K = sk[par];
        const float* V = sv[par];
        const ulonglong2* Q2 = (const ulonglong2*)(Q + C0);
        const ulonglong2* K2 = (const ulonglong2*)(K + C0);
        const ulonglong2* V2 = (const ulonglong2*)(V + C0);

        // ---- Phase 1: rank-1 updates Sqq += q q^T, Sqv += q v^T, fused with
        //      row partials au=(Sqq'k)_r, ap=(Sqv'v)_r, ag=(Jq)_r  (f32x2).
        const float qr = Q[r];
        const u64 qr2 = pack2(qr, qr);
        u64 au2 = 0ull, ap2 = 0ull, ag2 = 0ull;
#pragma unroll
        for (int i = 0; i < CP2 / 2; i++) {
            const ulonglong2 q2 = Q2[i], k2 = K2[i], v2 = V2[i];
            const int p = 2 * i;
            Sqq2[p]     = ffma2(qr2, q2.x, Sqq2[p]);
            au2         = ffma2(Sqq2[p], k2.x, au2);
            Sqv2[p]     = ffma2(qr2, v2.x, Sqv2[p]);
            ap2         = ffma2(Sqv2[p], v2.x, ap2);
            ag2         = ffma2(Jm2[p], q2.x, ag2);
            Sqq2[p + 1] = ffma2(qr2, q2.y, Sqq2[p + 1]);
            au2         = ffma2(Sqq2[p + 1], k2.y, au2);
            Sqv2[p + 1] = ffma2(qr2, v2.y, Sqv2[p + 1]);
            ap2         = ffma2(Sqv2[p + 1], v2.y, ap2);
            ag2         = ffma2(Jm2[p + 1], q2.y, ag2);
        }
        const float au = hadd2(au2), ap = hadd2(ap2), ag = hadd2(ag2);
        pu[sub * D + r] = au;
        pg[sub * D + r] = ag;
        // in-warp reductions for dots LINEAR in the partials:
        //   kp = k.(Sqv' v) = s_l,  ku = k.(Sqq' k),  vgd = v.(J q)
        {
            const float kr = K[r], vr = V[r];
            float t0 = kr * ap, t1 = kr * au, t2 = vr * ag;
#pragma unroll
            for (int off = 16; off; off >>= 1) {
                t0 += __shfl_down_sync(0xffffffffu, t0, off);
                t1 += __shfl_down_sync(0xffffffffu, t1, off);
                t2 += __shfl_down_sync(0xffffffffu, t2, off);
            }
            if (lane == 0) { wA0[par][warp] = t0; wA1[par][warp] = t1; wA2[par][warp] = t2; }
        }
        __syncthreads();   // A

        // ---- Phase 2 (warps 0-3): finish u = Sqq'k and g = Jq; publish u;
        //      reduce gg = g.g, vv = v.v. Also feed double buffer + prefetch.
        if (tid < D) {
            const float u = pu[tid] + pu[D + tid];
            const float g = pg[tid] + pg[D + tid];
            su[tid] = u;
            const float vt = V[tid];
            float t0 = g * g, t1 = vt * vt;
#pragma unroll
            for (int off = 16; off; off >>= 1) {
                t0 += __shfl_down_sync(0xffffffffu, t0, off);
                t1 += __shfl_down_sync(0xffffffffu, t1, off);
            }
            if (lane == 0) { wB0[par][warp] = t0; wB1[par][warp] = t1; }

            sq[nxt][tid] = rq; sk[nxt][tid] = rk; sv[nxt][tid] = rv;
            if (l + 2 < SEQ) {
                const int o = (l + 2) * D + tid;
                rq = qg[o]; rk = kg[o]; rv = vg[o];
            }
        }
        __syncthreads();   // B

        // ---- Phase 3: vw = v.(J u) = A_Jl
        {
            u64 aw2 = 0ull;
            const ulonglong2* U2 = (const ulonglong2*)(su + C0);
#pragma unroll
            for (int i = 0; i < CP2 / 2; i++) {
                const ulonglong2 u2 = U2[i];
                aw2 = ffma2(Jm2[2 * i], u2.x, aw2);
                aw2 = ffma2(Jm2[2 * i + 1], u2.y, aw2);
            }
            float t = hadd2(aw2) * V[r];
#pragma unroll
            for (int off = 16; off; off >>= 1)
                t += __shfl_down_sync(0xffffffffu, t, off);
            if (lane == 0) wC[par][warp] = t;
        }
        __syncthreads();   // C

        // ---- Phase 4 (ALL threads, redundant, bit-identical): fp32 decision.
        //      Broadcast LDS of per-warp partials; shadows from one step ago.
        float a, b, updf;
        {
            const float kp  = sum8(wA0[par]);
            const float ku  = sum8(wA1[par]);
            const float vgd = sum8(wA2[par]);
            const float vw  = sum8(wC[par]);
            const float4 B0 = *(const float4*)wB0[par];
            const float4 B1 = *(const float4*)wB1[par];
            const float gg  = (B0.x + B0.y) + (B0.z + B0.w);
            const float vv  = (B1.x + B1.y) + (B1.z + B1.w);

            const float AJJ = sTf[par][0] + gg;   // tr(J Sqq' J^T), old J
            const float sJc = sTf[par][1] + vgd;  // tr(J Sqv'), old J
            const float sl  = kp;                 // k^T Sqv' v
            const float All = vv * ku;            // (v.v)(k^T Sqq' k)
            const float AJl = vw;                 // v^T J Sqq' k

            const bool  first  = (l == 0);
            const float AJJs   = (first || AJJ == 0.f) ? 1.f : AJJ;
            const float Alls   = (first || All == 0.f) ? 1.f : All;
            const float denom  = AJJ * All - AJl * AJl;
            const float denoms = (first || denom == 0.f) ? 1.f : denom;

            const float ratio  = sJc / AJJs;
            const float margin = sl - AJl * ratio;
            const float invden = 1.f / denoms;
            const float wf = (All * sJc - AJl * sl) * invden;
            const float wi = (AJJ * sl - AJl * sJc) * invden;
            const float wfc = (wi <= 0.f) ? ratio : ((wf <= 0.f) ? 0.f : wf);
            const float wic = (wi <= 0.f) ? 0.f : ((wf <= 0.f) ? sl / Alls : wi);
            const bool dou = (margin > 0.f);

            if (first)    { a = 0.f; b = 1.f; }   // J = v k^T
            else if (dou) { a = wfc; b = wic; }
            else          { a = 1.f; b = 0.f; }
            updf = (first || dou) ? 1.f : 0.f;

            // Thread 0: exact fp64 state recurrence, shadow publish, outputs.
            // Runs concurrently with other warps' phase 5 / next phase 1.
            if (tid == 0) {
                const double AJJd = Tacc + (double)gg;
                const double sJcd = sJ + (double)vgd;
                const double sld  = (double)kp;
                const double Alld = (double)vv * (double)ku;
                const double AJld = (double)vw;
                trSvv += (double)vv;
                const double ad = (double)a, bd = (double)b;
                Tacc = ad * ad * AJJd + 2.0 * ad * bd * AJld + bd * bd * Alld;
                sJ   = ad * sJcd + bd * sld;
                sTf[nxt][0] = (float)Tacc;
                sTf[nxt][1] = (float)sJ;
                out[l]       = (float)(0.5 * trSvv - sJ + 0.5 * Tacc) / (float)(l + 1);
                out[SEQ + l] = updf;
            }
        }

        // ---- Phase 5: conditional rank-1 J update (registers, f32x2)
        if (updf != 0.f) {
            const u64 a2 = pack2(a, a);
            const float bvr = b * V[r];
            const u64 b2 = pack2(bvr, bvr);
#pragma unroll
            for (int i = 0; i < CP2 / 2; i++) {
                const ulonglong2 k2 = K2[i];
                Jm2[2 * i]     = ffma2(b2, k2.x, fmul2(a2, Jm2[2 * i]));
                Jm2[2 * i + 1] = ffma2(b2, k2.y, fmul2(a2, Jm2[2 * i + 1]));
            }
        }
    }

    // Emit final J [d_v, d_k] row-major.
#pragma unroll
    for (int p = 0; p < CP2; p++) {
        float x, y; unpack2(Jm2[p], x, y);
        out[2 * SEQ + r * D + C0 + 2 * p]     = x;
        out[2 * SEQ + r * D + C0 + 2 * p + 1] = y;
    }
}

extern "C" void kernel_launch(void* const* d_in, const int* in_sizes, int n_in,
                              void* d_out, int out_size)
{
    (void)in_sizes; (void)n_in; (void)out_size;
    gim_kernel<<<1, NT>>>((const float*)d_in[0], (const float*)d_in[1],
                          (const float*)d_in[2], (float*)d_out);
}